// round 3
// baseline (speedup 1.0000x reference)
#include <cuda_runtime.h>
#include <cuda_bf16.h>
#include <cstdint>

// CPLSTM_20959440405049 — constant-folded (proof: h0=0 and multiplicative gate
// g=(h@a)*(x@b) ==> g=0 ==> f=i=o=0.5, g_t=0 ==> h_t=c_t=0 exactly for all t).
// output = dec_b broadcast over (S*B, V); (c_T, h_T) = zeros. rel_err measured 0.0.
//
// Round 3: single fused launch. Threads whose column lies past V4 (the grid.x
// overshoot: 8192-8000 = 192 threads per row-tile) zero the 256 KB state tail
// instead of idling. Main path steady state = STG.128.cs + IADD only, ~90% of
// HBM write bandwidth.

__global__ void cplstm_fused_kernel(const float4* __restrict__ dec_b4,
                                    float4* __restrict__ out4,
                                    int V4,          // V/4 float4 columns per row
                                    int rows,        // S*B rows
                                    size_t tail_off4,// float4 offset of state tail
                                    size_t tail_n4)  // float4 count of state tail
{
    const int col4 = blockIdx.x * blockDim.x + threadIdx.x;

    if (col4 < V4) {
        const float4 v = dec_b4[col4];   // one load per thread, L2-resident

        float4* __restrict__ p = out4 + (size_t)blockIdx.y * V4 + col4;
        const size_t step = (size_t)gridDim.y * V4;

        int r = blockIdx.y;
        #pragma unroll 4
        for (; r < rows; r += gridDim.y) {
            __stcs(p, v);                // streaming store: 524 MB, zero reuse
            p += step;
        }
    } else {
        // Overshoot threads: zero the (c_T, h_T) tail in parallel.
        const int over = gridDim.x * blockDim.x - V4;     // idle threads per row-tile
        size_t i = (size_t)(col4 - V4) + (size_t)over * blockIdx.y;
        const size_t stride = (size_t)over * gridDim.y;
        const float4 z = make_float4(0.f, 0.f, 0.f, 0.f);
        for (; i < tail_n4; i += stride)
            __stcs(&out4[tail_off4 + i], z);
    }
}

// Defensive generic path (only if V % 4 != 0 or odd sizes — not this problem).
__global__ void cplstm_generic_kernel(const float* __restrict__ dec_b,
                                      float* __restrict__ out,
                                      size_t n_total, size_t n_logits, int V)
{
    size_t i = (size_t)blockIdx.x * blockDim.x + threadIdx.x;
    const size_t stride = (size_t)gridDim.x * blockDim.x;
    for (; i < n_total; i += stride) {
        float s = (i < n_logits) ? dec_b[i % (size_t)V] : 0.f;
        __stcs(&out[i], s);
    }
}

extern "C" void kernel_launch(void* const* d_in, const int* in_sizes, int n_in,
                              void* d_out, int out_size)
{
    // metadata order: inp(S,B) int32, emb(V,D), a(H,4R), b(D,4R), ct(4R,H),
    //                 dec_w(V,H), dec_b(V,)
    const float* dec_b = (const float*)d_in[6];
    float*       out   = (float*)d_out;

    const size_t SB = (size_t)in_sizes[0];   // S*B = 4096 rows
    const int    V  = in_sizes[6];           // 32000
    const size_t n_total = (size_t)out_size;
    size_t n_logits = SB * (size_t)V;
    if (n_logits > n_total) n_logits = n_total;

    const size_t n_tail = n_total - n_logits;

    if ((V & 3) != 0 || (n_logits & 3) != 0 || (n_tail & 3) != 0) {
        cplstm_generic_kernel<<<148 * 8, 256>>>(dec_b, out, n_total, n_logits, V);
        return;
    }

    const int V4   = V >> 2;                 // 8000 float4 per row
    const int rows = (int)SB;                // 4096

    // grid.x = 32 blocks x 256 threads = 8192 column slots (>= 8000); the 192
    // overshoot threads per row-tile handle the tail. grid.y = 64 -> 2048 CTAs
    // (~1.7 waves at 8 CTA/SM), 64 stores per main-path thread.
    dim3 block(256, 1, 1);
    dim3 grid((V4 + 255) / 256, 64, 1);

    // Guarantee at least some overshoot threads exist for the tail; with
    // V4=8000 there are 192 per row-tile. If V4 were an exact multiple of
    // blockDim, add one extra column block.
    if ((int)grid.x * 256 == V4 && n_tail > 0) grid.x += 1;

    cplstm_fused_kernel<<<grid, block>>>(
        (const float4*)dec_b, (float4*)out, V4, rows,
        n_logits >> 2, n_tail >> 2);
}

// round 4
// speedup vs baseline: 1.0749x; 1.0749x over previous
#include <cuda_runtime.h>
#include <cuda_bf16.h>
#include <cstdint>

// CPLSTM_20959440405049 — constant-folded (proof: h0=0 and the multiplicative
// gate g=(h@a)*(x_t@b) give g=0 ==> f=i=o=sigmoid(0)=0.5, g_t=tanh(0)=0 ==>
// c'=0.5*0+0.5*0=0, h'=0.5*tanh(0)=0; by induction h_t=c_t=0 exactly for all t).
// output = dec_b broadcast over (S*B, V); (c_T, h_T) = zeros. rel_err = 0.0.
//
// Round 4: fused single launch (Round-3 win) + grid.y=128 geometry (Round-2
// win: 4096 CTAs / 32 stores per thread measured faster than 2048/64 — more
// concurrent store streams = better DRAM bank/page parallelism).

__global__ void cplstm_fused_kernel(const float4* __restrict__ dec_b4,
                                    float4* __restrict__ out4,
                                    int V4,           // V/4 float4 columns per row
                                    int rows,         // S*B rows
                                    size_t tail_off4, // float4 offset of state tail
                                    size_t tail_n4)   // float4 count of state tail
{
    const int col4 = blockIdx.x * blockDim.x + threadIdx.x;

    if (col4 < V4) {
        const float4 v = dec_b4[col4];   // one load per thread, L2-resident

        float4* __restrict__ p = out4 + (size_t)blockIdx.y * V4 + col4;
        const size_t step = (size_t)gridDim.y * V4;

        int r = blockIdx.y;
        #pragma unroll 4
        for (; r < rows; r += gridDim.y) {
            __stcs(p, v);                // streaming store: 524 MB, zero reuse
            p += step;
        }
    } else {
        // Overshoot threads (grid.x*256 - V4 per row-tile) zero the 256 KB
        // (c_T, h_T) tail in parallel with the main stream.
        const int over = gridDim.x * blockDim.x - V4;
        size_t i = (size_t)(col4 - V4) + (size_t)over * blockIdx.y;
        const size_t stride = (size_t)over * gridDim.y;
        const float4 z = make_float4(0.f, 0.f, 0.f, 0.f);
        for (; i < tail_n4; i += stride)
            __stcs(&out4[tail_off4 + i], z);
    }
}

// Defensive generic path (only if V % 4 != 0 or odd sizes — not this problem).
__global__ void cplstm_generic_kernel(const float* __restrict__ dec_b,
                                      float* __restrict__ out,
                                      size_t n_total, size_t n_logits, int V)
{
    size_t i = (size_t)blockIdx.x * blockDim.x + threadIdx.x;
    const size_t stride = (size_t)gridDim.x * blockDim.x;
    for (; i < n_total; i += stride) {
        float s = (i < n_logits) ? dec_b[i % (size_t)V] : 0.f;
        __stcs(&out[i], s);
    }
}

extern "C" void kernel_launch(void* const* d_in, const int* in_sizes, int n_in,
                              void* d_out, int out_size)
{
    // metadata order: inp(S,B) int32, emb(V,D), a(H,4R), b(D,4R), ct(4R,H),
    //                 dec_w(V,H), dec_b(V,)
    const float* dec_b = (const float*)d_in[6];
    float*       out   = (float*)d_out;

    const size_t SB = (size_t)in_sizes[0];   // S*B = 4096 rows
    const int    V  = in_sizes[6];           // 32000
    const size_t n_total = (size_t)out_size;
    size_t n_logits = SB * (size_t)V;
    if (n_logits > n_total) n_logits = n_total;

    const size_t n_tail = n_total - n_logits;

    if ((V & 3) != 0 || (n_logits & 3) != 0 || (n_tail & 3) != 0) {
        cplstm_generic_kernel<<<148 * 8, 256>>>(dec_b, out, n_total, n_logits, V);
        return;
    }

    const int V4   = V >> 2;                 // 8000 float4 per row
    const int rows = (int)SB;                // 4096

    // grid.x = 32 blocks x 256 threads = 8192 column slots (>= 8000); the 192
    // overshoot threads per row-tile zero the tail. grid.y = 128 -> 4096 CTAs,
    // 32 stores per main-path thread (measured-best geometry from Round 2).
    dim3 block(256, 1, 1);
    dim3 grid((V4 + 255) / 256, 128, 1);

    // If V4 were an exact multiple of blockDim there'd be no overshoot threads;
    // add one extra column block so the tail still gets written.
    if ((int)grid.x * 256 == V4 && n_tail > 0) grid.x += 1;

    cplstm_fused_kernel<<<grid, block>>>(
        (const float4*)dec_b, (float4*)out, V4, rows,
        n_logits >> 2, n_tail >> 2);
}

// round 5
// speedup vs baseline: 1.1144x; 1.0367x over previous
#include <cuda_runtime.h>
#include <cuda_bf16.h>
#include <cstdint>

// CPLSTM_20959440405049 — constant-folded (proof: h0=0 and the multiplicative
// gate g=(h@a)*(x_t@b) give g=0 ==> f=i=o=sigmoid(0)=0.5, g_t=tanh(0)=0 ==>
// c'=0.5*0+0.5*0=0, h'=0.5*tanh(0)=0; by induction h_t=c_t=0 exactly for all t).
// output = dec_b broadcast over (S*B, V); (c_T, h_T) = zeros. rel_err = 0.0.
//
// Round 5: same fused single-launch kernel; grid.y 128 -> 256 following the
// measured monotone trend (64: 81.1us/72.3% DRAM, 128: 76.9us/76.3% DRAM).
// More concurrent store streams -> more DRAM bank/page parallelism. Steady
// state per thread: STG.128.cs + IADD, 16 independent stores.

__global__ void cplstm_fused_kernel(const float4* __restrict__ dec_b4,
                                    float4* __restrict__ out4,
                                    int V4,           // V/4 float4 columns per row
                                    int rows,         // S*B rows
                                    size_t tail_off4, // float4 offset of state tail
                                    size_t tail_n4)   // float4 count of state tail
{
    const int col4 = blockIdx.x * blockDim.x + threadIdx.x;

    if (col4 < V4) {
        const float4 v = dec_b4[col4];   // one load per thread, L2-resident

        float4* __restrict__ p = out4 + (size_t)blockIdx.y * V4 + col4;
        const size_t step = (size_t)gridDim.y * V4;

        int r = blockIdx.y;
        #pragma unroll 4
        for (; r < rows; r += gridDim.y) {
            __stcs(p, v);                // streaming store: 524 MB, zero reuse
            p += step;
        }
    } else {
        // Overshoot threads (grid.x*256 - V4 per row-tile) zero the 256 KB
        // (c_T, h_T) tail in parallel with the main stream.
        const int over = gridDim.x * blockDim.x - V4;
        size_t i = (size_t)(col4 - V4) + (size_t)over * blockIdx.y;
        const size_t stride = (size_t)over * gridDim.y;
        const float4 z = make_float4(0.f, 0.f, 0.f, 0.f);
        for (; i < tail_n4; i += stride)
            __stcs(&out4[tail_off4 + i], z);
    }
}

// Defensive generic path (only if V % 4 != 0 or odd sizes — not this problem).
__global__ void cplstm_generic_kernel(const float* __restrict__ dec_b,
                                      float* __restrict__ out,
                                      size_t n_total, size_t n_logits, int V)
{
    size_t i = (size_t)blockIdx.x * blockDim.x + threadIdx.x;
    const size_t stride = (size_t)gridDim.x * blockDim.x;
    for (; i < n_total; i += stride) {
        float s = (i < n_logits) ? dec_b[i % (size_t)V] : 0.f;
        __stcs(&out[i], s);
    }
}

extern "C" void kernel_launch(void* const* d_in, const int* in_sizes, int n_in,
                              void* d_out, int out_size)
{
    // metadata order: inp(S,B) int32, emb(V,D), a(H,4R), b(D,4R), ct(4R,H),
    //                 dec_w(V,H), dec_b(V,)
    const float* dec_b = (const float*)d_in[6];
    float*       out   = (float*)d_out;

    const size_t SB = (size_t)in_sizes[0];   // S*B = 4096 rows
    const int    V  = in_sizes[6];           // 32000
    const size_t n_total = (size_t)out_size;
    size_t n_logits = SB * (size_t)V;
    if (n_logits > n_total) n_logits = n_total;

    const size_t n_tail = n_total - n_logits;

    if ((V & 3) != 0 || (n_logits & 3) != 0 || (n_tail & 3) != 0) {
        cplstm_generic_kernel<<<148 * 8, 256>>>(dec_b, out, n_total, n_logits, V);
        return;
    }

    const int V4   = V >> 2;                 // 8000 float4 per row
    const int rows = (int)SB;                // 4096

    // grid.x = 32 blocks x 256 threads = 8192 column slots (>= 8000); the 192
    // overshoot threads per row-tile zero the tail. grid.y = 256 -> 8192 CTAs,
    // 16 stores per main-path thread.
    dim3 block(256, 1, 1);
    int gy = 256;
    if (gy > rows) gy = rows;                // never exceed row count
    dim3 grid((V4 + 255) / 256, gy, 1);

    // If V4 were an exact multiple of blockDim there'd be no overshoot threads;
    // add one extra column block so the tail still gets written.
    if ((int)grid.x * 256 == V4 && n_tail > 0) grid.x += 1;

    cplstm_fused_kernel<<<grid, block>>>(
        (const float4*)dec_b, (float4*)out, V4, rows,
        n_logits >> 2, n_tail >> 2);
}

// round 6
// speedup vs baseline: 1.1438x; 1.0264x over previous
#include <cuda_runtime.h>
#include <cuda_bf16.h>
#include <cstdint>

// CPLSTM_20959440405049 — constant-folded (proof: h0=0 and the multiplicative
// gate g=(h@a)*(x_t@b) give g=0 ==> f=i=o=sigmoid(0)=0.5, g_t=tanh(0)=0 ==>
// c'=0.5*0+0.5*0=0, h'=0.5*tanh(0)=0; by induction h_t=c_t=0 exactly for all t).
// output = dec_b broadcast over (S*B, V); (c_T, h_T) = zeros. rel_err = 0.0.
//
// Round 6: grid.y 256 -> 512, following the measured monotone series
// (64: 81.1us/72.3%, 128: 76.9/76.3%, 256: 73.2/80.2%). More concurrent
// store streams -> more open DRAM row streams per channel. Steady state per
// thread: STG.128.cs + IADD, 8 independent stores.

__global__ void cplstm_fused_kernel(const float4* __restrict__ dec_b4,
                                    float4* __restrict__ out4,
                                    int V4,           // V/4 float4 columns per row
                                    int rows,         // S*B rows
                                    size_t tail_off4, // float4 offset of state tail
                                    size_t tail_n4)   // float4 count of state tail
{
    const int col4 = blockIdx.x * blockDim.x + threadIdx.x;

    if (col4 < V4) {
        const float4 v = dec_b4[col4];   // one load per thread, L2-resident

        float4* __restrict__ p = out4 + (size_t)blockIdx.y * V4 + col4;
        const size_t step = (size_t)gridDim.y * V4;

        int r = blockIdx.y;
        #pragma unroll 4
        for (; r < rows; r += gridDim.y) {
            __stcs(p, v);                // streaming store: 524 MB, zero reuse
            p += step;
        }
    } else {
        // Overshoot threads (grid.x*256 - V4 per row-tile) zero the 256 KB
        // (c_T, h_T) tail in parallel with the main stream.
        const int over = gridDim.x * blockDim.x - V4;
        size_t i = (size_t)(col4 - V4) + (size_t)over * blockIdx.y;
        const size_t stride = (size_t)over * gridDim.y;
        const float4 z = make_float4(0.f, 0.f, 0.f, 0.f);
        for (; i < tail_n4; i += stride)
            __stcs(&out4[tail_off4 + i], z);
    }
}

// Defensive generic path (only if V % 4 != 0 or odd sizes — not this problem).
__global__ void cplstm_generic_kernel(const float* __restrict__ dec_b,
                                      float* __restrict__ out,
                                      size_t n_total, size_t n_logits, int V)
{
    size_t i = (size_t)blockIdx.x * blockDim.x + threadIdx.x;
    const size_t stride = (size_t)gridDim.x * blockDim.x;
    for (; i < n_total; i += stride) {
        float s = (i < n_logits) ? dec_b[i % (size_t)V] : 0.f;
        __stcs(&out[i], s);
    }
}

extern "C" void kernel_launch(void* const* d_in, const int* in_sizes, int n_in,
                              void* d_out, int out_size)
{
    // metadata order: inp(S,B) int32, emb(V,D), a(H,4R), b(D,4R), ct(4R,H),
    //                 dec_w(V,H), dec_b(V,)
    const float* dec_b = (const float*)d_in[6];
    float*       out   = (float*)d_out;

    const size_t SB = (size_t)in_sizes[0];   // S*B = 4096 rows
    const int    V  = in_sizes[6];           // 32000
    const size_t n_total = (size_t)out_size;
    size_t n_logits = SB * (size_t)V;
    if (n_logits > n_total) n_logits = n_total;

    const size_t n_tail = n_total - n_logits;

    if ((V & 3) != 0 || (n_logits & 3) != 0 || (n_tail & 3) != 0) {
        cplstm_generic_kernel<<<148 * 8, 256>>>(dec_b, out, n_total, n_logits, V);
        return;
    }

    const int V4   = V >> 2;                 // 8000 float4 per row
    const int rows = (int)SB;                // 4096

    // grid.x = 32 blocks x 256 threads = 8192 column slots (>= 8000); the 192
    // overshoot threads per row-tile zero the tail. grid.y = 512 -> 16384 CTAs,
    // 8 stores per main-path thread.
    dim3 block(256, 1, 1);
    int gy = 512;
    if (gy > rows) gy = rows;                // never exceed row count
    dim3 grid((V4 + 255) / 256, gy, 1);

    // If V4 were an exact multiple of blockDim there'd be no overshoot threads;
    // add one extra column block so the tail still gets written.
    if ((int)grid.x * 256 == V4 && n_tail > 0) grid.x += 1;

    cplstm_fused_kernel<<<grid, block>>>(
        (const float4*)dec_b, (float4*)out, V4, rows,
        n_logits >> 2, n_tail >> 2);
}

// round 7
// speedup vs baseline: 1.1448x; 1.0009x over previous
#include <cuda_runtime.h>
#include <cuda_bf16.h>
#include <cstdint>

// CPLSTM_20959440405049 — constant-folded (proof: h0=0 and the multiplicative
// gate g=(h@a)*(x_t@b) give g=0 ==> f=i=o=sigmoid(0)=0.5, g_t=tanh(0)=0 ==>
// c'=0.5*0+0.5*0=0, h'=0.5*tanh(0)=0; by induction h_t=c_t=0 exactly for all t).
// output = dec_b broadcast over (S*B, V); (c_T, h_T) = zeros. rel_err = 0.0.
//
// Round 7: stream-count knob is saturated (256->512 CTAs gained only 0.5us,
// DRAM stuck ~80%). Hypothesis: TLB reach (256MB) < output (524MB) and the
// interleaved row mapping makes EVERY store touch a distinct 2MB page
// (stride gridDim.y*32KB = 64MB). Switch to contiguous row-chunk mapping:
// CTA (x,y) writes rows [y*CHUNK, y*CHUNK+CHUNK) — a thread's stores span
// 256KB (1-2 pages), collapsing live page set ~8x.

__global__ void cplstm_fused_kernel(const float4* __restrict__ dec_b4,
                                    float4* __restrict__ out4,
                                    int V4,           // V/4 float4 columns per row
                                    int rows,         // S*B rows
                                    int chunk,        // contiguous rows per CTA-y
                                    size_t tail_off4, // float4 offset of state tail
                                    size_t tail_n4)   // float4 count of state tail
{
    const int col4 = blockIdx.x * blockDim.x + threadIdx.x;

    if (col4 < V4) {
        const float4 v = dec_b4[col4];   // one load per thread, L2-resident

        const int r0   = blockIdx.y * chunk;
        int rend = r0 + chunk;
        if (rend > rows) rend = rows;

        float4* __restrict__ p = out4 + (size_t)r0 * V4 + col4;
        #pragma unroll 4
        for (int r = r0; r < rend; ++r) {
            __stcs(p, v);                // streaming store: 524 MB, zero reuse
            p += V4;                     // +32 KB: stays within 1-2 pages/thread
        }
    } else {
        // Overshoot threads (grid.x*256 - V4 per row-tile) zero the 256 KB
        // (c_T, h_T) tail in parallel with the main stream.
        const int over = gridDim.x * blockDim.x - V4;
        size_t i = (size_t)(col4 - V4) + (size_t)over * blockIdx.y;
        const size_t stride = (size_t)over * gridDim.y;
        const float4 z = make_float4(0.f, 0.f, 0.f, 0.f);
        for (; i < tail_n4; i += stride)
            __stcs(&out4[tail_off4 + i], z);
    }
}

// Defensive generic path (only if V % 4 != 0 or odd sizes — not this problem).
__global__ void cplstm_generic_kernel(const float* __restrict__ dec_b,
                                      float* __restrict__ out,
                                      size_t n_total, size_t n_logits, int V)
{
    size_t i = (size_t)blockIdx.x * blockDim.x + threadIdx.x;
    const size_t stride = (size_t)gridDim.x * blockDim.x;
    for (; i < n_total; i += stride) {
        float s = (i < n_logits) ? dec_b[i % (size_t)V] : 0.f;
        __stcs(&out[i], s);
    }
}

extern "C" void kernel_launch(void* const* d_in, const int* in_sizes, int n_in,
                              void* d_out, int out_size)
{
    // metadata order: inp(S,B) int32, emb(V,D), a(H,4R), b(D,4R), ct(4R,H),
    //                 dec_w(V,H), dec_b(V,)
    const float* dec_b = (const float*)d_in[6];
    float*       out   = (float*)d_out;

    const size_t SB = (size_t)in_sizes[0];   // S*B = 4096 rows
    const int    V  = in_sizes[6];           // 32000
    const size_t n_total = (size_t)out_size;
    size_t n_logits = SB * (size_t)V;
    if (n_logits > n_total) n_logits = n_total;

    const size_t n_tail = n_total - n_logits;

    if ((V & 3) != 0 || (n_logits & 3) != 0 || (n_tail & 3) != 0) {
        cplstm_generic_kernel<<<148 * 8, 256>>>(dec_b, out, n_total, n_logits, V);
        return;
    }

    const int V4   = V >> 2;                 // 8000 float4 per row
    const int rows = (int)SB;                // 4096

    // grid.x = 32 col blocks (8192 slots >= 8000; 192 overshoot threads per
    // row-tile zero the tail). grid.y = 512 chunks x 8 contiguous rows each
    // (same 16384-CTA geometry as the Round-6 plateau; only mapping changes).
    dim3 block(256, 1, 1);
    int gy = 512;
    if (gy > rows) gy = rows;
    const int chunk = (rows + gy - 1) / gy;  // 8
    dim3 grid((V4 + 255) / 256, gy, 1);

    if ((int)grid.x * 256 == V4 && n_tail > 0) grid.x += 1;

    cplstm_fused_kernel<<<grid, block>>>(
        (const float4*)dec_b, (float4*)out, V4, rows, chunk,
        n_logits >> 2, n_tail >> 2);
}